// round 1
// baseline (speedup 1.0000x reference)
#include <cuda_runtime.h>

#define BB 4
#define NN 4096
#define DD 16
#define CC 128
#define TILE 128
#define NT (NN / TILE)     /* 32 */
#define HALF_M (NN / 2)    /* 2048 */

typedef unsigned long long ull;

__device__ __align__(16) float g_Q[BB * NN * DD];
__device__ __align__(16) float g_K[BB * NN * DD];
__device__ __align__(16) float g_V[BB * NN * DD];
__device__ float g_rowinv[BB * NN];
__device__ float g_colinv[BB * NN];
__device__ float g_T[BB * DD * NN];
__device__ float g_part[BB * NT * 8];

__device__ __forceinline__ ull pack2(float lo, float hi) {
    ull r; asm("mov.b64 %0, {%1, %2};" : "=l"(r) : "f"(lo), "f"(hi)); return r;
}
__device__ __forceinline__ void unpack2(ull v, float& lo, float& hi) {
    asm("mov.b64 {%0, %1}, %2;" : "=f"(lo), "=f"(hi) : "l"(v));
}
__device__ __forceinline__ ull fma2(ull a, ull b, ull c) {
    ull d; asm("fma.rn.f32x2 %0, %1, %2, %3;" : "=l"(d) : "l"(a), "l"(b), "l"(c)); return d;
}

// 16-element dot: q in registers (8 packed f32x2), k from shared (vectorized LDS.128).
__device__ __forceinline__ float dot16(const ull* q, const float* kp) {
    const ulonglong2* k2 = (const ulonglong2*)kp;
    ull a0 = 0ULL, a1 = 0ULL;
#pragma unroll
    for (int i = 0; i < 4; i++) {
        ulonglong2 kk = k2[i];
        a0 = fma2(q[2 * i], kk.x, a0);
        a1 = fma2(q[2 * i + 1], kk.y, a1);
    }
    float x, y, z, w; unpack2(a0, x, y); unpack2(a1, z, w);
    return (x + y) + (z + w);
}

// ---------------------------------------------------------------------------
// Kernel 1: projections. q = w_qk@x_q + pos_q ; k = w_qk@x_kv + pos_kv ;
// v = w_v@x_kv + b_v + pos_kv. Stored row-major [b][n][16].
// ---------------------------------------------------------------------------
__global__ void proj_kernel(const float* __restrict__ x_q, const float* __restrict__ x_kv,
                            const float* __restrict__ xyz_q, const float* __restrict__ xyz_kv,
                            const float* __restrict__ w_qk, const float* __restrict__ w_v,
                            const float* __restrict__ b_v,
                            const float* __restrict__ w_pos_q, const float* __restrict__ w_pos_kv) {
    __shared__ __align__(16) float s_wqk[CC][DD];
    __shared__ __align__(16) float s_wv[CC][DD];
    const int b = blockIdx.z;
    const int isKV = blockIdx.y;
    const int n = blockIdx.x * TILE + threadIdx.x;
    for (int i = threadIdx.x; i < CC * DD; i += TILE) {
        int d = i / CC, c = i % CC;  // weights are [D][C] row-major
        s_wqk[c][d] = w_qk[i];
        s_wv[c][d] = w_v[i];
    }
    __syncthreads();
    if (isKV == 0) {
        float p0 = xyz_q[(b * 3 + 0) * NN + n];
        float p1 = xyz_q[(b * 3 + 1) * NN + n];
        float p2 = xyz_q[(b * 3 + 2) * NN + n];
        float acc[DD];
#pragma unroll
        for (int d = 0; d < DD; d++)
            acc[d] = w_pos_q[d * 3] * p0 + w_pos_q[d * 3 + 1] * p1 + w_pos_q[d * 3 + 2] * p2;
        const float* xp = x_q + (size_t)b * CC * NN + n;
#pragma unroll 4
        for (int c = 0; c < CC; c++) {
            float xv = xp[(size_t)c * NN];
            const float4* w4 = (const float4*)s_wqk[c];
#pragma unroll
            for (int i = 0; i < 4; i++) {
                float4 w = w4[i];
                acc[4 * i + 0] += w.x * xv; acc[4 * i + 1] += w.y * xv;
                acc[4 * i + 2] += w.z * xv; acc[4 * i + 3] += w.w * xv;
            }
        }
        float4* qp = (float4*)(g_Q + ((size_t)(b * NN + n)) * DD);
#pragma unroll
        for (int i = 0; i < 4; i++)
            qp[i] = make_float4(acc[4 * i], acc[4 * i + 1], acc[4 * i + 2], acc[4 * i + 3]);
    } else {
        float p0 = xyz_kv[(b * 3 + 0) * NN + n];
        float p1 = xyz_kv[(b * 3 + 1) * NN + n];
        float p2 = xyz_kv[(b * 3 + 2) * NN + n];
        float ak[DD], av[DD];
#pragma unroll
        for (int d = 0; d < DD; d++) {
            float pos = w_pos_kv[d * 3] * p0 + w_pos_kv[d * 3 + 1] * p1 + w_pos_kv[d * 3 + 2] * p2;
            ak[d] = pos;
            av[d] = pos + b_v[d];
        }
        const float* xp = x_kv + (size_t)b * CC * NN + n;
#pragma unroll 2
        for (int c = 0; c < CC; c++) {
            float xv = xp[(size_t)c * NN];
            const float4* wq4 = (const float4*)s_wqk[c];
            const float4* wv4 = (const float4*)s_wv[c];
#pragma unroll
            for (int i = 0; i < 4; i++) {
                float4 wq = wq4[i], wv = wv4[i];
                ak[4 * i + 0] += wq.x * xv; ak[4 * i + 1] += wq.y * xv;
                ak[4 * i + 2] += wq.z * xv; ak[4 * i + 3] += wq.w * xv;
                av[4 * i + 0] += wv.x * xv; av[4 * i + 1] += wv.y * xv;
                av[4 * i + 2] += wv.z * xv; av[4 * i + 3] += wv.w * xv;
            }
        }
        float4* kp = (float4*)(g_K + ((size_t)(b * NN + n)) * DD);
        float4* vp = (float4*)(g_V + ((size_t)(b * NN + n)) * DD);
#pragma unroll
        for (int i = 0; i < 4; i++) {
            kp[i] = make_float4(ak[4 * i], ak[4 * i + 1], ak[4 * i + 2], ak[4 * i + 3]);
            vp[i] = make_float4(av[4 * i], av[4 * i + 1], av[4 * i + 2], av[4 * i + 3]);
        }
    }
}

// ---------------------------------------------------------------------------
// Kernel 2: rowsum[n] = sum_m exp(q[n]·k[m]).  Thread owns one row, half of m.
// exp is overflow-safe without max subtraction (|e| <~ 10 << 88).
// ---------------------------------------------------------------------------
__global__ void rowsum_kernel() {
    __shared__ __align__(16) float sk[2][TILE * DD];
    __shared__ float sred[256];
    const int b = blockIdx.y;
    const int tid = threadIdx.x;
    const int lane127 = tid & 127;
    const int row = blockIdx.x * TILE + lane127;
    const int half = tid >> 7;

    ull qr[8];
    {
        const ulonglong2* qp = (const ulonglong2*)(g_Q + ((size_t)(b * NN + row)) * DD);
#pragma unroll
        for (int i = 0; i < 4; i++) { ulonglong2 t = qp[i]; qr[2 * i] = t.x; qr[2 * i + 1] = t.y; }
    }
    const float* kbase = g_K + ((size_t)b * NN + (size_t)half * HALF_M) * DD;
    float sum0 = 0.f, sum1 = 0.f;
    for (int it = 0; it < HALF_M / TILE; ++it) {
        __syncthreads();
        {
            float4* dst = (float4*)sk[half];
            const float4* src = (const float4*)(kbase + it * TILE * DD);
#pragma unroll
            for (int k = 0; k < 4; k++) dst[lane127 + k * TILE] = src[lane127 + k * TILE];
        }
        __syncthreads();
        const float* ks = sk[half];
#pragma unroll 4
        for (int mm = 0; mm < TILE; mm += 2) {
            float e0 = dot16(qr, ks + mm * DD);
            float e1 = dot16(qr, ks + mm * DD + DD);
            sum0 += __expf(e0);
            sum1 += __expf(e1);
        }
    }
    sred[tid] = sum0 + sum1;
    __syncthreads();
    if (half == 0) {
        float tot = sred[tid] + sred[tid + 128];
        g_rowinv[b * NN + row] = 1.0f / tot;
    }
}

// ---------------------------------------------------------------------------
// Kernel 3: colsum[m] = sum_n exp(e[n,m]) * rowinv[n].  Thread owns a column.
// ---------------------------------------------------------------------------
__global__ void colsum_kernel() {
    __shared__ __align__(16) float sq[2][TILE * DD];
    __shared__ float sri[2][TILE];
    __shared__ float sred[256];
    const int b = blockIdx.y;
    const int tid = threadIdx.x;
    const int lane127 = tid & 127;
    const int col = blockIdx.x * TILE + lane127;
    const int half = tid >> 7;

    ull kr[8];
    {
        const ulonglong2* kp = (const ulonglong2*)(g_K + ((size_t)(b * NN + col)) * DD);
#pragma unroll
        for (int i = 0; i < 4; i++) { ulonglong2 t = kp[i]; kr[2 * i] = t.x; kr[2 * i + 1] = t.y; }
    }
    const float* qbase = g_Q + ((size_t)b * NN + (size_t)half * HALF_M) * DD;
    const float* ribase = g_rowinv + b * NN + half * HALF_M;
    float sum0 = 0.f, sum1 = 0.f;
    for (int it = 0; it < HALF_M / TILE; ++it) {
        __syncthreads();
        {
            float4* dst = (float4*)sq[half];
            const float4* src = (const float4*)(qbase + it * TILE * DD);
#pragma unroll
            for (int k = 0; k < 4; k++) dst[lane127 + k * TILE] = src[lane127 + k * TILE];
            sri[half][lane127] = ribase[it * TILE + lane127];
        }
        __syncthreads();
        const float* qs = sq[half];
        const float* ri = sri[half];
#pragma unroll 4
        for (int nn2 = 0; nn2 < TILE; nn2 += 2) {
            float e0 = dot16(kr, qs + nn2 * DD);
            float e1 = dot16(kr, qs + nn2 * DD + DD);
            sum0 += __expf(e0) * ri[nn2];
            sum1 += __expf(e1) * ri[nn2 + 1];
        }
    }
    sred[tid] = sum0 + sum1;
    __syncthreads();
    if (half == 0) {
        float tot = sred[tid] + sred[tid + 128];
        g_colinv[b * NN + col] = 1.0f / (1e-9f + tot);
    }
}

// ---------------------------------------------------------------------------
// Kernel 4: x_r[n,:] = rowinv[n] * sum_m exp(e)*colinv[m]*v[m,:]; then
// t = w_t @ (q - x_r) + b_t, write t, and deterministic per-(b,group) partial
// sums for GroupNorm stats.
// ---------------------------------------------------------------------------
__global__ void pass3_kernel(const float* __restrict__ w_t, const float* __restrict__ b_t) {
    __shared__ __align__(16) float sk[2][TILE * DD];
    __shared__ __align__(16) float sv[2][TILE * DD];
    __shared__ float sci[2][TILE];
    __shared__ __align__(16) float sxr[TILE * DD];
    __shared__ float swt[DD * DD];
    const int b = blockIdx.y;
    const int tid = threadIdx.x;
    const int lane127 = tid & 127;
    const int row = blockIdx.x * TILE + lane127;
    const int half = tid >> 7;

    swt[tid] = w_t[tid];  // blockDim == 256 == DD*DD

    ull qr[8];
    {
        const ulonglong2* qp = (const ulonglong2*)(g_Q + ((size_t)(b * NN + row)) * DD);
#pragma unroll
        for (int i = 0; i < 4; i++) { ulonglong2 t = qp[i]; qr[2 * i] = t.x; qr[2 * i + 1] = t.y; }
    }
    const float* kbase = g_K + ((size_t)b * NN + (size_t)half * HALF_M) * DD;
    const float* vbase = g_V + ((size_t)b * NN + (size_t)half * HALF_M) * DD;
    const float* cibase = g_colinv + b * NN + half * HALF_M;
    ull xr[8];
#pragma unroll
    for (int i = 0; i < 8; i++) xr[i] = 0ULL;

    for (int it = 0; it < HALF_M / TILE; ++it) {
        __syncthreads();
        {
            float4* dk = (float4*)sk[half];
            float4* dv = (float4*)sv[half];
            const float4* srck = (const float4*)(kbase + it * TILE * DD);
            const float4* srcv = (const float4*)(vbase + it * TILE * DD);
#pragma unroll
            for (int k = 0; k < 4; k++) {
                dk[lane127 + k * TILE] = srck[lane127 + k * TILE];
                dv[lane127 + k * TILE] = srcv[lane127 + k * TILE];
            }
            sci[half][lane127] = cibase[it * TILE + lane127];
        }
        __syncthreads();
        const float* ks = sk[half];
        const float* vs = sv[half];
        const float* ci = sci[half];
#pragma unroll 2
        for (int mm = 0; mm < TILE; ++mm) {
            float e = dot16(qr, ks + mm * DD);
            float w = __expf(e) * ci[mm];
            ull w2 = pack2(w, w);
            const ulonglong2* v2 = (const ulonglong2*)(vs + mm * DD);
#pragma unroll
            for (int i = 0; i < 4; i++) {
                ulonglong2 vv = v2[i];
                xr[2 * i] = fma2(w2, vv.x, xr[2 * i]);
                xr[2 * i + 1] = fma2(w2, vv.y, xr[2 * i + 1]);
            }
        }
    }
    __syncthreads();
    if (half == 1) {
        ull* dst = (ull*)(sxr + lane127 * DD);
#pragma unroll
        for (int i = 0; i < 8; i++) dst[i] = xr[i];
    }
    __syncthreads();
    float* red = (float*)sk;  // reuse: 1024 floats needed
    if (half == 0) {
        float rinv = g_rowinv[b * NN + row];
        const ull* oth = (const ull*)(sxr + lane127 * DD);
        float xrf[DD], qf[DD];
#pragma unroll
        for (int i = 0; i < 8; i++) {
            float a, c2; unpack2(xr[i], a, c2);
            float bo, d2; unpack2(oth[i], bo, d2);
            xrf[2 * i] = (a + bo) * rinv;
            xrf[2 * i + 1] = (c2 + d2) * rinv;
            float ql, qh; unpack2(qr[i], ql, qh);
            qf[2 * i] = ql; qf[2 * i + 1] = qh;
        }
        float diff[DD];
#pragma unroll
        for (int d = 0; d < DD; d++) diff[d] = qf[d] - xrf[d];
        float gs[4] = {0.f, 0.f, 0.f, 0.f}, gs2[4] = {0.f, 0.f, 0.f, 0.f};
#pragma unroll
        for (int o = 0; o < DD; o++) {
            float s = b_t[o];
#pragma unroll
            for (int d = 0; d < DD; d++) s += swt[o * DD + d] * diff[d];
            g_T[((size_t)(b * DD + o)) * NN + row] = s;
            gs[o >> 2] += s;
            gs2[o >> 2] += s * s;
        }
#pragma unroll
        for (int g = 0; g < 4; g++) {
            red[lane127 * 8 + g] = gs[g];
            red[lane127 * 8 + 4 + g] = gs2[g];
        }
    }
    __syncthreads();
    for (int s = 64; s > 0; s >>= 1) {
        if (tid < s) {
#pragma unroll
            for (int j = 0; j < 8; j++) red[tid * 8 + j] += red[(tid + s) * 8 + j];
        }
        __syncthreads();
    }
    if (tid < 8) g_part[((size_t)(b * NT + blockIdx.x)) * 8 + tid] = red[tid];
}

// ---------------------------------------------------------------------------
// Kernel 5: finalize GN stats (deterministic), relu, + q^T.
// ---------------------------------------------------------------------------
__global__ void final_kernel(const float* __restrict__ gamma, const float* __restrict__ beta,
                             float* __restrict__ out) {
    __shared__ float sq[TILE * 17];  // padded transpose buffer for q
    __shared__ float ssc[DD], ssh[DD];
    const int b = blockIdx.y;
    const int tid = threadIdx.x;
    const int n0 = blockIdx.x * TILE;
    if (tid < DD) {
        int g = tid >> 2;
        float s = 0.f, s2 = 0.f;
        for (int t = 0; t < NT; t++) {
            s += g_part[(b * NT + t) * 8 + g];
            s2 += g_part[(b * NT + t) * 8 + 4 + g];
        }
        float cnt = (float)(4 * NN);
        float mean = s / cnt;
        float var = s2 / cnt - mean * mean;
        float inv = rsqrtf(var + 1e-5f);
        float sc = gamma[tid] * inv;
        ssc[tid] = sc;
        ssh[tid] = beta[tid] - mean * sc;
    }
    const float* qsrc = g_Q + ((size_t)(b * NN + n0)) * DD;
    for (int i = tid; i < TILE * DD; i += 256) sq[(i >> 4) * 17 + (i & 15)] = qsrc[i];
    __syncthreads();
    for (int i = tid; i < TILE * DD; i += 256) {
        int c = i >> 7, j = i & 127;
        size_t idx = ((size_t)(b * DD + c)) * NN + n0 + j;
        float tv = g_T[idx];
        float r = fmaxf(tv * ssc[c] + ssh[c], 0.f);
        out[idx] = r + sq[j * 17 + c];
    }
}

extern "C" void kernel_launch(void* const* d_in, const int* in_sizes, int n_in,
                              void* d_out, int out_size) {
    const float* x_q      = (const float*)d_in[0];
    const float* x_kv     = (const float*)d_in[1];
    const float* xyz_q    = (const float*)d_in[2];
    const float* xyz_kv   = (const float*)d_in[3];
    const float* w_qk     = (const float*)d_in[4];
    const float* w_v      = (const float*)d_in[5];
    const float* b_v      = (const float*)d_in[6];
    const float* w_t      = (const float*)d_in[7];
    const float* b_t      = (const float*)d_in[8];
    const float* gamma    = (const float*)d_in[9];
    const float* beta     = (const float*)d_in[10];
    const float* w_pos_q  = (const float*)d_in[11];
    const float* w_pos_kv = (const float*)d_in[12];
    float* out = (float*)d_out;

    proj_kernel<<<dim3(NT, 2, BB), TILE>>>(x_q, x_kv, xyz_q, xyz_kv, w_qk, w_v, b_v,
                                           w_pos_q, w_pos_kv);
    rowsum_kernel<<<dim3(NT, BB), 256>>>();
    colsum_kernel<<<dim3(NT, BB), 256>>>();
    pass3_kernel<<<dim3(NT, BB), 256>>>(w_t, b_t);
    final_kernel<<<dim3(NT, BB), 256>>>(gamma, beta, out);
}

// round 2
// speedup vs baseline: 2.2843x; 2.2843x over previous
#include <cuda_runtime.h>

#define BB 4
#define NN 4096
#define DD 16
#define CC 128
#define NT 32
#define LOG2E 1.4426950408889634f

typedef unsigned long long ull;

__device__ __align__(16) float g_Q[BB * NN * DD];
__device__ __align__(16) float g_K[BB * NN * DD];   // pre-scaled by log2(e)
__device__ __align__(16) float g_V[BB * NN * DD];
__device__ float g_rowinv[BB * NN];
__device__ float g_colinv[BB * NN];
__device__ float g_T[BB * DD * NN];
__device__ float g_part[BB * NT * 8];

__device__ __forceinline__ ull pack2(float lo, float hi) {
    ull r; asm("mov.b64 %0, {%1, %2};" : "=l"(r) : "f"(lo), "f"(hi)); return r;
}
__device__ __forceinline__ void unpack2(ull v, float& lo, float& hi) {
    asm("mov.b64 {%0, %1}, %2;" : "=f"(lo), "=f"(hi) : "l"(v));
}
__device__ __forceinline__ ull fma2(ull a, ull b, ull c) {
    ull d; asm("fma.rn.f32x2 %0, %1, %2, %3;" : "=l"(d) : "l"(a), "l"(b), "l"(c)); return d;
}
__device__ __forceinline__ ull add2(ull a, ull b) {
    ull d; asm("add.rn.f32x2 %0, %1, %2;" : "=l"(d) : "l"(a), "l"(b)); return d;
}
__device__ __forceinline__ float ex2(float x) {
    float y; asm("ex2.approx.ftz.f32 %0, %1;" : "=f"(y) : "f"(x)); return y;
}

// dot of one q row (8 packed f32x2 regs) with k (8 packed f32x2 regs)
__device__ __forceinline__ float dotrr(const ull* q, const ull* kk) {
    ull a0 = fma2(q[0], kk[0], 0ULL);
    ull a1 = fma2(q[1], kk[1], 0ULL);
#pragma unroll
    for (int i = 1; i < 4; i++) {
        a0 = fma2(q[2 * i], kk[2 * i], a0);
        a1 = fma2(q[2 * i + 1], kk[2 * i + 1], a1);
    }
    ull s = add2(a0, a1);
    float x, y; unpack2(s, x, y);
    return x + y;
}

__device__ __forceinline__ void load_rows4(ull dst[4][8], const float* base) {
    const ulonglong2* p = (const ulonglong2*)base;
#pragma unroll
    for (int r = 0; r < 4; r++)
#pragma unroll
        for (int i = 0; i < 4; i++) {
            ulonglong2 t = p[r * 4 + i];
            dst[r][2 * i] = t.x; dst[r][2 * i + 1] = t.y;
        }
}

// ---------------------------------------------------------------------------
// Kernel 1: projections. Q raw; K scaled by log2(e); V = wv@x + b_v + pos.
// ---------------------------------------------------------------------------
__global__ void proj_kernel(const float* __restrict__ x_q, const float* __restrict__ x_kv,
                            const float* __restrict__ xyz_q, const float* __restrict__ xyz_kv,
                            const float* __restrict__ w_qk, const float* __restrict__ w_v,
                            const float* __restrict__ b_v,
                            const float* __restrict__ w_pos_q, const float* __restrict__ w_pos_kv) {
    __shared__ __align__(16) float s_wqk[CC][DD];
    __shared__ __align__(16) float s_wv[CC][DD];
    const int b = blockIdx.z;
    const int isKV = blockIdx.y;
    const int n = blockIdx.x * 128 + threadIdx.x;
    for (int i = threadIdx.x; i < CC * DD; i += 128) {
        int d = i / CC, c = i % CC;
        s_wqk[c][d] = w_qk[i];
        s_wv[c][d] = w_v[i];
    }
    __syncthreads();
    if (isKV == 0) {
        float p0 = xyz_q[(b * 3 + 0) * NN + n];
        float p1 = xyz_q[(b * 3 + 1) * NN + n];
        float p2 = xyz_q[(b * 3 + 2) * NN + n];
        float acc[DD];
#pragma unroll
        for (int d = 0; d < DD; d++)
            acc[d] = w_pos_q[d * 3] * p0 + w_pos_q[d * 3 + 1] * p1 + w_pos_q[d * 3 + 2] * p2;
        const float* xp = x_q + (size_t)b * CC * NN + n;
#pragma unroll 4
        for (int c = 0; c < CC; c++) {
            float xv = xp[(size_t)c * NN];
            const float4* w4 = (const float4*)s_wqk[c];
#pragma unroll
            for (int i = 0; i < 4; i++) {
                float4 w = w4[i];
                acc[4 * i + 0] += w.x * xv; acc[4 * i + 1] += w.y * xv;
                acc[4 * i + 2] += w.z * xv; acc[4 * i + 3] += w.w * xv;
            }
        }
        float4* qp = (float4*)(g_Q + ((size_t)(b * NN + n)) * DD);
#pragma unroll
        for (int i = 0; i < 4; i++)
            qp[i] = make_float4(acc[4 * i], acc[4 * i + 1], acc[4 * i + 2], acc[4 * i + 3]);
    } else {
        float p0 = xyz_kv[(b * 3 + 0) * NN + n];
        float p1 = xyz_kv[(b * 3 + 1) * NN + n];
        float p2 = xyz_kv[(b * 3 + 2) * NN + n];
        float ak[DD], av[DD];
#pragma unroll
        for (int d = 0; d < DD; d++) {
            float pos = w_pos_kv[d * 3] * p0 + w_pos_kv[d * 3 + 1] * p1 + w_pos_kv[d * 3 + 2] * p2;
            ak[d] = pos;
            av[d] = pos + b_v[d];
        }
        const float* xp = x_kv + (size_t)b * CC * NN + n;
#pragma unroll 2
        for (int c = 0; c < CC; c++) {
            float xv = xp[(size_t)c * NN];
            const float4* wq4 = (const float4*)s_wqk[c];
            const float4* wv4 = (const float4*)s_wv[c];
#pragma unroll
            for (int i = 0; i < 4; i++) {
                float4 wq = wq4[i], wv = wv4[i];
                ak[4 * i + 0] += wq.x * xv; ak[4 * i + 1] += wq.y * xv;
                ak[4 * i + 2] += wq.z * xv; ak[4 * i + 3] += wq.w * xv;
                av[4 * i + 0] += wv.x * xv; av[4 * i + 1] += wv.y * xv;
                av[4 * i + 2] += wv.z * xv; av[4 * i + 3] += wv.w * xv;
            }
        }
        float4* kp = (float4*)(g_K + ((size_t)(b * NN + n)) * DD);
        float4* vp = (float4*)(g_V + ((size_t)(b * NN + n)) * DD);
#pragma unroll
        for (int i = 0; i < 4; i++) {
            kp[i] = make_float4(ak[4 * i] * LOG2E, ak[4 * i + 1] * LOG2E,
                                ak[4 * i + 2] * LOG2E, ak[4 * i + 3] * LOG2E);
            vp[i] = make_float4(av[4 * i], av[4 * i + 1], av[4 * i + 2], av[4 * i + 3]);
        }
    }
}

// ---------------------------------------------------------------------------
// Kernel 2: rowsum. Block: 128 rows. Lane = 4 rows in regs; warp = m-range.
// ---------------------------------------------------------------------------
__global__ __launch_bounds__(256, 1) void rowsum_kernel() {
    __shared__ __align__(16) float sk[8][64 * DD];
    __shared__ float sred[8][128];
    const int tid = threadIdx.x, lane = tid & 31, w = tid >> 5;
    const int b = blockIdx.y;
    const int row0 = blockIdx.x * 128 + lane * 4;

    ull qr[4][8];
    load_rows4(qr, g_Q + ((size_t)(b * NN + row0)) * DD);

    const float* kbase = g_K + ((size_t)b * NN + (size_t)w * 512) * DD;
    float sum[4] = {0.f, 0.f, 0.f, 0.f};
    for (int it = 0; it < 8; ++it) {
        __syncwarp();
        {
            float4* dst = (float4*)sk[w];
            const float4* src = (const float4*)(kbase + it * 64 * DD);
#pragma unroll
            for (int j = 0; j < 8; j++) dst[lane + j * 32] = src[lane + j * 32];
        }
        __syncwarp();
#pragma unroll 4
        for (int mm = 0; mm < 64; ++mm) {
            ull kk[8];
            const ulonglong2* k2 = (const ulonglong2*)(sk[w] + mm * DD);
#pragma unroll
            for (int i = 0; i < 4; i++) { ulonglong2 t = k2[i]; kk[2 * i] = t.x; kk[2 * i + 1] = t.y; }
#pragma unroll
            for (int r = 0; r < 4; r++) sum[r] += ex2(dotrr(qr[r], kk));
        }
    }
#pragma unroll
    for (int r = 0; r < 4; r++) sred[w][lane * 4 + r] = sum[r];
    __syncthreads();
    if (tid < 128) {
        float tot = 0.f;
#pragma unroll
        for (int j = 0; j < 8; j++) tot += sred[j][tid];
        g_rowinv[b * NN + blockIdx.x * 128 + tid] = 1.0f / tot;
    }
}

// ---------------------------------------------------------------------------
// Kernel 3: colsum. Lane = 4 cols (k in regs); warp = n-range (q staged).
// ---------------------------------------------------------------------------
__global__ __launch_bounds__(256, 1) void colsum_kernel() {
    __shared__ __align__(16) float sq[8][64 * DD];
    __shared__ float sri[8][64];
    __shared__ float sred[8][128];
    const int tid = threadIdx.x, lane = tid & 31, w = tid >> 5;
    const int b = blockIdx.y;
    const int col0 = blockIdx.x * 128 + lane * 4;

    ull kr[4][8];
    load_rows4(kr, g_K + ((size_t)(b * NN + col0)) * DD);

    const float* qbase = g_Q + ((size_t)b * NN + (size_t)w * 512) * DD;
    const float* ribase = g_rowinv + b * NN + w * 512;
    float sum[4] = {0.f, 0.f, 0.f, 0.f};
    for (int it = 0; it < 8; ++it) {
        __syncwarp();
        {
            float4* dst = (float4*)sq[w];
            const float4* src = (const float4*)(qbase + it * 64 * DD);
#pragma unroll
            for (int j = 0; j < 8; j++) dst[lane + j * 32] = src[lane + j * 32];
            sri[w][lane] = ribase[it * 64 + lane];
            sri[w][lane + 32] = ribase[it * 64 + lane + 32];
        }
        __syncwarp();
#pragma unroll 4
        for (int nn2 = 0; nn2 < 64; ++nn2) {
            ull kk[8];
            const ulonglong2* q2 = (const ulonglong2*)(sq[w] + nn2 * DD);
#pragma unroll
            for (int i = 0; i < 4; i++) { ulonglong2 t = q2[i]; kk[2 * i] = t.x; kk[2 * i + 1] = t.y; }
            float ri = sri[w][nn2];
#pragma unroll
            for (int r = 0; r < 4; r++) sum[r] += ex2(dotrr(kr[r], kk)) * ri;
        }
    }
#pragma unroll
    for (int r = 0; r < 4; r++) sred[w][lane * 4 + r] = sum[r];
    __syncthreads();
    if (tid < 128) {
        float tot = 0.f;
#pragma unroll
        for (int j = 0; j < 8; j++) tot += sred[j][tid];
        g_colinv[b * NN + blockIdx.x * 128 + tid] = 1.0f / (1e-9f + tot);
    }
}

// ---------------------------------------------------------------------------
// Kernel 4: AV sweep + w_t transform + GN partial stats.
// ---------------------------------------------------------------------------
__global__ __launch_bounds__(256, 1) void pass3_kernel(const float* __restrict__ w_t,
                                                       const float* __restrict__ b_t) {
    __shared__ __align__(16) float sbig[8192];   // 32KB: per-warp k/v tiles, then xr slots
    __shared__ float sci[8][32];
    __shared__ float swt[256];
    __shared__ float sred[1024];
    const int tid = threadIdx.x, lane = tid & 31, w = tid >> 5;
    const int b = blockIdx.y;
    const int row0 = blockIdx.x * 128 + lane * 4;

    swt[tid] = w_t[tid];

    ull qr[4][8];
    load_rows4(qr, g_Q + ((size_t)(b * NN + row0)) * DD);

    const float* kbase = g_K + ((size_t)b * NN + (size_t)w * 512) * DD;
    const float* vbase = g_V + ((size_t)b * NN + (size_t)w * 512) * DD;
    const float* cibase = g_colinv + b * NN + w * 512;
    float* skw = sbig + w * 1024;        // 32 m x 16
    float* svw = skw + 512;

    ull xr[4][8];
#pragma unroll
    for (int r = 0; r < 4; r++)
#pragma unroll
        for (int i = 0; i < 8; i++) xr[r][i] = 0ULL;

    for (int it = 0; it < 16; ++it) {
        __syncwarp();
        {
            float4* dk = (float4*)skw;
            float4* dv = (float4*)svw;
            const float4* srck = (const float4*)(kbase + it * 32 * DD);
            const float4* srcv = (const float4*)(vbase + it * 32 * DD);
#pragma unroll
            for (int j = 0; j < 4; j++) {
                dk[lane + j * 32] = srck[lane + j * 32];
                dv[lane + j * 32] = srcv[lane + j * 32];
            }
            sci[w][lane] = cibase[it * 32 + lane];
        }
        __syncwarp();
#pragma unroll 2
        for (int mm = 0; mm < 32; ++mm) {
            ull kk[8];
            const ulonglong2* k2 = (const ulonglong2*)(skw + mm * DD);
#pragma unroll
            for (int i = 0; i < 4; i++) { ulonglong2 t = k2[i]; kk[2 * i] = t.x; kk[2 * i + 1] = t.y; }
            float ci = sci[w][mm];
            float wgt[4];
#pragma unroll
            for (int r = 0; r < 4; r++) wgt[r] = ex2(dotrr(qr[r], kk)) * ci;
            ull vv[8];
            const ulonglong2* v2 = (const ulonglong2*)(svw + mm * DD);
#pragma unroll
            for (int i = 0; i < 4; i++) { ulonglong2 t = v2[i]; vv[2 * i] = t.x; vv[2 * i + 1] = t.y; }
#pragma unroll
            for (int r = 0; r < 4; r++) {
                ull w2 = pack2(wgt[r], wgt[r]);
#pragma unroll
                for (int i = 0; i < 8; i++) xr[r][i] = fma2(w2, vv[i], xr[r][i]);
            }
        }
    }

    // reduce xr across 8 warps in two rounds using sbig (4 slots x 128 rows x 16)
    __syncthreads();
    if (w >= 4) {
        ull* d = (ull*)(sbig + ((size_t)(w - 4) * 128 + lane * 4) * DD);
#pragma unroll
        for (int r = 0; r < 4; r++)
#pragma unroll
            for (int i = 0; i < 8; i++) d[r * 8 + i] = xr[r][i];
    }
    __syncthreads();
    if (w < 4) {
        ull* d = (ull*)(sbig + ((size_t)w * 128 + lane * 4) * DD);
#pragma unroll
        for (int r = 0; r < 4; r++)
#pragma unroll
            for (int i = 0; i < 8; i++) d[r * 8 + i] = add2(d[r * 8 + i], xr[r][i]);
    }
    __syncthreads();

    if (tid < 128) {
        const int row = blockIdx.x * 128 + tid;
        float rinv = g_rowinv[b * NN + row];
        float xrf[DD];
        const float* s0 = sbig + tid * DD;
#pragma unroll
        for (int d = 0; d < DD; d++)
            xrf[d] = (s0[d] + s0[2048 + d] + s0[4096 + d] + s0[6144 + d]) * rinv;
        const float* qg = g_Q + ((size_t)(b * NN + row)) * DD;
        float diff[DD];
#pragma unroll
        for (int d = 0; d < DD; d++) diff[d] = qg[d] - xrf[d];
        float gs[4] = {0.f, 0.f, 0.f, 0.f}, gs2[4] = {0.f, 0.f, 0.f, 0.f};
#pragma unroll
        for (int o = 0; o < DD; o++) {
            float s = b_t[o];
#pragma unroll
            for (int d = 0; d < DD; d++) s += swt[o * DD + d] * diff[d];
            g_T[((size_t)(b * DD + o)) * NN + row] = s;
            gs[o >> 2] += s;
            gs2[o >> 2] += s * s;
        }
#pragma unroll
        for (int g = 0; g < 4; g++) {
            sred[tid * 8 + g] = gs[g];
            sred[tid * 8 + 4 + g] = gs2[g];
        }
    }
    __syncthreads();
    for (int s = 64; s > 0; s >>= 1) {
        if (tid < s) {
#pragma unroll
            for (int j = 0; j < 8; j++) sred[tid * 8 + j] += sred[(tid + s) * 8 + j];
        }
        __syncthreads();
    }
    if (tid < 8) g_part[((size_t)(b * NT + blockIdx.x)) * 8 + tid] = sred[tid];
}

// ---------------------------------------------------------------------------
// Kernel 5: finalize GN stats, relu, + q^T.
// ---------------------------------------------------------------------------
__global__ void final_kernel(const float* __restrict__ gamma, const float* __restrict__ beta,
                             float* __restrict__ out) {
    __shared__ float sq[128 * 17];
    __shared__ float ssc[DD], ssh[DD];
    const int b = blockIdx.y;
    const int tid = threadIdx.x;
    const int n0 = blockIdx.x * 128;
    if (tid < DD) {
        int g = tid >> 2;
        float s = 0.f, s2 = 0.f;
        for (int t = 0; t < NT; t++) {
            s += g_part[(b * NT + t) * 8 + g];
            s2 += g_part[(b * NT + t) * 8 + 4 + g];
        }
        float cnt = (float)(4 * NN);
        float mean = s / cnt;
        float var = s2 / cnt - mean * mean;
        float inv = rsqrtf(var + 1e-5f);
        float sc = gamma[tid] * inv;
        ssc[tid] = sc;
        ssh[tid] = beta[tid] - mean * sc;
    }
    const float* qsrc = g_Q + ((size_t)(b * NN + n0)) * DD;
    for (int i = tid; i < 128 * DD; i += 256) sq[(i >> 4) * 17 + (i & 15)] = qsrc[i];
    __syncthreads();
    for (int i = tid; i < 128 * DD; i += 256) {
        int c = i >> 7, j = i & 127;
        size_t idx = ((size_t)(b * DD + c)) * NN + n0 + j;
        float tv = g_T[idx];
        float r = fmaxf(tv * ssc[c] + ssh[c], 0.f);
        out[idx] = r + sq[j * 17 + c];
    }
}

extern "C" void kernel_launch(void* const* d_in, const int* in_sizes, int n_in,
                              void* d_out, int out_size) {
    const float* x_q      = (const float*)d_in[0];
    const float* x_kv     = (const float*)d_in[1];
    const float* xyz_q    = (const float*)d_in[2];
    const float* xyz_kv   = (const float*)d_in[3];
    const float* w_qk     = (const float*)d_in[4];
    const float* w_v      = (const float*)d_in[5];
    const float* b_v      = (const float*)d_in[6];
    const float* w_t      = (const float*)d_in[7];
    const float* b_t      = (const float*)d_in[8];
    const float* gamma    = (const float*)d_in[9];
    const float* beta     = (const float*)d_in[10];
    const float* w_pos_q  = (const float*)d_in[11];
    const float* w_pos_kv = (const float*)d_in[12];
    float* out = (float*)d_out;

    proj_kernel<<<dim3(NT, 2, BB), 128>>>(x_q, x_kv, xyz_q, xyz_kv, w_qk, w_v, b_v,
                                          w_pos_q, w_pos_kv);
    rowsum_kernel<<<dim3(NT, BB), 256>>>();
    colsum_kernel<<<dim3(NT, BB), 256>>>();
    pass3_kernel<<<dim3(NT, BB), 256>>>(w_t, b_t);
    final_kernel<<<dim3(NT, BB), 256>>>(gamma, beta, out);
}